// round 12
// baseline (speedup 1.0000x reference)
#include <cuda_runtime.h>
#include <cuda_bf16.h>
#include <cstdint>

// Problem constants
#define SQ   4096
#define DM   1024
#define NH   16
#define HDIM 64

// ---------------------------------------------------------------------------
// Scratch (allocation-free rule: __device__ globals) — all bf16 hi/lo pairs
// ---------------------------------------------------------------------------
__device__ __align__(16) __nv_bfloat16 g_xh[SQ * DM];
__device__ __align__(16) __nv_bfloat16 g_xl[SQ * DM];
__device__ __align__(16) __nv_bfloat16 g_wh[4][DM * DM];
__device__ __align__(16) __nv_bfloat16 g_wl[4][DM * DM];
__device__ __align__(16) __nv_bfloat16 g_qh[SQ * DM];   // pre-scaled by 0.125
__device__ __align__(16) __nv_bfloat16 g_ql[SQ * DM];
__device__ __align__(16) __nv_bfloat16 g_kh[SQ * DM];
__device__ __align__(16) __nv_bfloat16 g_kl[SQ * DM];
__device__ __align__(16) __nv_bfloat16 g_vh[SQ * DM];
__device__ __align__(16) __nv_bfloat16 g_vl[SQ * DM];
__device__ __align__(16) __nv_bfloat16 g_ch[SQ * DM];
__device__ __align__(16) __nv_bfloat16 g_cl[SQ * DM];

// ---------------------------------------------------------------------------
// PTX helpers (legacy / non-'a' instructions only: HMMA, ldmatrix, cp.async)
// ---------------------------------------------------------------------------
__device__ __forceinline__ uint32_t smem_to_u32(const void* p) {
    uint32_t a;
    asm("{ .reg .u64 t; cvta.to.shared.u64 t, %1; cvt.u32.u64 %0, t; }"
        : "=r"(a) : "l"(p));
    return a;
}

__device__ __forceinline__ void mma16816(float* c, const uint32_t* a, const uint32_t* b)
{
    asm volatile(
        "mma.sync.aligned.m16n8k16.row.col.f32.bf16.bf16.f32 "
        "{%0,%1,%2,%3}, {%4,%5,%6,%7}, {%8,%9}, {%0,%1,%2,%3};\n"
        : "+f"(c[0]), "+f"(c[1]), "+f"(c[2]), "+f"(c[3])
        : "r"(a[0]), "r"(a[1]), "r"(a[2]), "r"(a[3]), "r"(b[0]), "r"(b[1]));
}

__device__ __forceinline__ void ldsm4(uint32_t* r, uint32_t addr)
{
    asm volatile("ldmatrix.sync.aligned.m8n8.x4.shared.b16 {%0,%1,%2,%3}, [%4];"
        : "=r"(r[0]), "=r"(r[1]), "=r"(r[2]), "=r"(r[3]) : "r"(addr));
}

__device__ __forceinline__ void ldsm4t(uint32_t* r, uint32_t addr)
{
    asm volatile("ldmatrix.sync.aligned.m8n8.x4.trans.shared.b16 {%0,%1,%2,%3}, [%4];"
        : "=r"(r[0]), "=r"(r[1]), "=r"(r[2]), "=r"(r[3]) : "r"(addr));
}

__device__ __forceinline__ void cp16(uint32_t dst, const void* src)
{
    asm volatile("cp.async.ca.shared.global [%0], [%1], 16;" :: "r"(dst), "l"(src));
}
#define CP_COMMIT() asm volatile("cp.async.commit_group;" ::: "memory")
#define CP_WAIT0()  asm volatile("cp.async.wait_group 0;" ::: "memory")
#define CP_WAIT1()  asm volatile("cp.async.wait_group 1;" ::: "memory")

#define PAIR_BAR(id) asm volatile("bar.sync %0, 64;" :: "r"(id) : "memory")

__device__ __forceinline__ uint32_t packbf(float lo, float hi)
{
    uint32_t r;
    asm("cvt.rn.bf16x2.f32 %0, %1, %2;" : "=r"(r) : "f"(hi), "f"(lo));
    return r;
}

// ---------------------------------------------------------------------------
// fp32 -> bf16 hi/lo splitters
// ---------------------------------------------------------------------------
__device__ __forceinline__ void split_pair(const float2 v, __nv_bfloat16* hi,
                                           __nv_bfloat16* lo, int i)
{
    __nv_bfloat16 h0 = __float2bfloat16(v.x);
    __nv_bfloat16 h1 = __float2bfloat16(v.y);
    __nv_bfloat16 l0 = __float2bfloat16(v.x - __bfloat162float(h0));
    __nv_bfloat16 l1 = __float2bfloat16(v.y - __bfloat162float(h1));
    ((__nv_bfloat162*)hi)[i] = __halves2bfloat162(h0, h1);
    ((__nv_bfloat162*)lo)[i] = __halves2bfloat162(l0, l1);
}

__global__ void split_x(const float* __restrict__ src, int n2)
{
    int i = blockIdx.x * blockDim.x + threadIdx.x;
    if (i >= n2) return;
    split_pair(((const float2*)src)[i], g_xh, g_xl, i);
}

__global__ void split_w(const float* __restrict__ w0, const float* __restrict__ w1,
                        const float* __restrict__ w2, const float* __restrict__ w3,
                        int n2)
{
    int wi = blockIdx.y;
    const float* src = (wi == 0) ? w0 : (wi == 1) ? w1 : (wi == 2) ? w2 : w3;
    int i = blockIdx.x * blockDim.x + threadIdx.x;
    if (i >= n2) return;
    split_pair(((const float2*)src)[i], g_wh[wi], g_wl[wi], i);
}

// ---------------------------------------------------------------------------
// HMMA GEMM: C[4096,1024] = A[4096,1024] * B[1024,1024]^T
// 2-stage cp.async, 2 CTAs/SM (smem 80KB, regs capped by launch_bounds(256,2)).
// BK=32 per iteration (2 k16 halves).
// ---------------------------------------------------------------------------
#define GSTR 40
#define GARR (128 * GSTR)              // 5120 bf16 = 10240 B
#define NSTG 2
#define TCG_SMEM (int)(NSTG * 4 * GARR * sizeof(__nv_bfloat16))   // 81920 B

__global__ __launch_bounds__(256, 2)
void tc_gemm(int asel, int wsel, int csel, float* Cparam, const float* bias)
{
    extern __shared__ __nv_bfloat16 smem[];
    const uint32_t sbase = smem_to_u32(smem);

    if (gridDim.z == 3) { wsel = blockIdx.z; csel = blockIdx.z; }

    const __nv_bfloat16* GAh = asel ? g_ch : g_xh;
    const __nv_bfloat16* GAl = asel ? g_cl : g_xl;
    const __nv_bfloat16* GBh = g_wh[wsel];
    const __nv_bfloat16* GBl = g_wl[wsel];

    const int tid  = threadIdx.x;
    const int wid  = tid >> 5;
    const int lane = tid & 31;
    const int wm   = wid >> 2;
    const int wn   = wid & 3;
    const int lr4  = lane >> 2;
    const int kq   = lane & 3;
    const int m0   = blockIdx.y * 128;
    const int n0   = blockIdx.x * 128;

    const int lrow0 = tid >> 2;
    const int lch   = tid & 3;
    const uint32_t sd0 = (uint32_t)(lrow0 * GSTR + lch * 8) * 2;
    const uint32_t sd1 = (uint32_t)((lrow0 + 64) * GSTR + lch * 8) * 2;

    const uint32_t aoff = (uint32_t)((wm * 64 + (lane & 15)) * GSTR + ((lane >> 4) & 1) * 8) * 2;
    const uint32_t boff = (uint32_t)((wn * 32 + (lane & 7) + ((lane >> 4) & 1) * 8) * GSTR
                                     + ((lane >> 3) & 1) * 8) * 2;

    float c[4][4][4];
#pragma unroll
    for (int i = 0; i < 4; i++)
#pragma unroll
        for (int j = 0; j < 4; j++)
#pragma unroll
            for (int e = 0; e < 4; e++) c[i][j][e] = 0.f;

#define ISSUE_STAGE(t) do { \
        uint32_t sb_ = sbase + (uint32_t)(((t) % NSTG) * 4 * GARR) * 2; \
        size_t koA0_ = (size_t)(m0 + lrow0) * DM + (size_t)(t) * 32 + lch * 8; \
        size_t koA1_ = (size_t)(m0 + lrow0 + 64) * DM + (size_t)(t) * 32 + lch * 8; \
        size_t koB0_ = (size_t)(n0 + lrow0) * DM + (size_t)(t) * 32 + lch * 8; \
        size_t koB1_ = (size_t)(n0 + lrow0 + 64) * DM + (size_t)(t) * 32 + lch * 8; \
        cp16(sb_ + sd0,                GAh + koA0_); \
        cp16(sb_ + sd1,                GAh + koA1_); \
        cp16(sb_ + GARR * 2 + sd0,     GAl + koA0_); \
        cp16(sb_ + GARR * 2 + sd1,     GAl + koA1_); \
        cp16(sb_ + 2 * GARR * 2 + sd0, GBh + koB0_); \
        cp16(sb_ + 2 * GARR * 2 + sd1, GBh + koB1_); \
        cp16(sb_ + 3 * GARR * 2 + sd0, GBl + koB0_); \
        cp16(sb_ + 3 * GARR * 2 + sd1, GBl + koB1_); \
        CP_COMMIT(); \
    } while (0)

    ISSUE_STAGE(0);
    ISSUE_STAGE(1);

    for (int t = 0; t < 32; t++) {
        if (t == 31) CP_WAIT0(); else CP_WAIT1();
        __syncthreads();

        const uint32_t stg = sbase + (uint32_t)((t % NSTG) * 4 * GARR) * 2;

#pragma unroll
        for (int kh = 0; kh < 2; kh++) {
            const uint32_t ko = (uint32_t)(kh * 16) * 2;
            uint32_t ah[4][4], al[4][4], bh[2][4], bl[2][4];
#pragma unroll
            for (int i = 0; i < 4; i++) {
                ldsm4(ah[i], stg + aoff + ko + (uint32_t)(i * 16 * GSTR) * 2);
                ldsm4(al[i], stg + GARR * 2 + aoff + ko + (uint32_t)(i * 16 * GSTR) * 2);
            }
#pragma unroll
            for (int jj = 0; jj < 2; jj++) {
                ldsm4(bh[jj], stg + 2 * GARR * 2 + boff + ko + (uint32_t)(jj * 16 * GSTR) * 2);
                ldsm4(bl[jj], stg + 3 * GARR * 2 + boff + ko + (uint32_t)(jj * 16 * GSTR) * 2);
            }

#pragma unroll
            for (int i = 0; i < 4; i++)
#pragma unroll
                for (int j = 0; j < 4; j++) {
                    const uint32_t* fh = bh[j >> 1] + (j & 1) * 2;
                    const uint32_t* fl = bl[j >> 1] + (j & 1) * 2;
                    mma16816(c[i][j], ah[i], fh);
                    mma16816(c[i][j], ah[i], fl);
                    mma16816(c[i][j], al[i], fh);
                }
        }

        __syncthreads();                  // all warps done with slot t%2
        if (t + 2 < 32) ISSUE_STAGE(t + 2);
    }
#undef ISSUE_STAGE

    if (csel < 3) {
        __nv_bfloat16* Hd = (csel == 0) ? g_qh : (csel == 1) ? g_kh : g_vh;
        __nv_bfloat16* Ld = (csel == 0) ? g_ql : (csel == 1) ? g_kl : g_vl;
        const float scale = (csel == 0) ? 0.125f : 1.0f;
#pragma unroll
        for (int i = 0; i < 4; i++) {
            int r = m0 + wm * 64 + i * 16 + lr4;
#pragma unroll
            for (int j = 0; j < 4; j++) {
                int col = n0 + wn * 32 + j * 8 + kq * 2;
#pragma unroll
                for (int half = 0; half < 2; half++) {
                    int rr = r + half * 8;
                    float v0 = c[i][j][half * 2 + 0] * scale;
                    float v1 = c[i][j][half * 2 + 1] * scale;
                    __nv_bfloat16 h0 = __float2bfloat16(v0);
                    __nv_bfloat16 h1 = __float2bfloat16(v1);
                    __nv_bfloat16 l0 = __float2bfloat16(v0 - __bfloat162float(h0));
                    __nv_bfloat16 l1 = __float2bfloat16(v1 - __bfloat162float(h1));
                    *(__nv_bfloat162*)&Hd[(size_t)rr * DM + col] = __halves2bfloat162(h0, h1);
                    *(__nv_bfloat162*)&Ld[(size_t)rr * DM + col] = __halves2bfloat162(l0, l1);
                }
            }
        }
    } else {
#pragma unroll
        for (int i = 0; i < 4; i++) {
            int r = m0 + wm * 64 + i * 16 + lr4;
#pragma unroll
            for (int j = 0; j < 4; j++) {
                int col = n0 + wn * 32 + j * 8 + kq * 2;
                float bx = bias[col], by = bias[col + 1];
                *(float2*)(Cparam + (size_t)r * DM + col)       = make_float2(c[i][j][0] + bx, c[i][j][1] + by);
                *(float2*)(Cparam + (size_t)(r + 8) * DM + col) = make_float2(c[i][j][2] + bx, c[i][j][3] + by);
            }
        }
    }
}

// ---------------------------------------------------------------------------
// MMA flash attention, causal. 512 threads, 16 warps in 8 pairs.
// Pair (wp, wp+8): same 16 query rows; side 0 = KV cols 0..63, side 1 = 64..127.
// Softmax max/sum exchanged through pbuf + named pair barriers.
// O partials combined in epilogue via smem (reusing KV region).
// ---------------------------------------------------------------------------
#define ASTR 72
#define ATILE (128 * ASTR)              // 9216 bf16
#define PBUF_B (2 * ATILE + 2 * 4 * ATILE) * 2   // byte offset of pbuf = 184320
#define ATTN_SMEM (int)(PBUF_B + 2048)

__device__ __forceinline__ void kv_load(uint32_t sbase, int tid, int kb, int buf, int hoff)
{
#pragma unroll
    for (int i = 0; i < 8; i++) {
        int id  = tid + 512 * i;
        int arr = id >> 10;
        int rem = id & 1023;
        int row = rem >> 3;
        int ch  = rem & 7;
        const __nv_bfloat16* src =
            ((arr == 0) ? g_kh : (arr == 1) ? g_kl : (arr == 2) ? g_vh : g_vl)
            + (size_t)(kb * 128 + row) * DM + hoff + ch * 8;
        uint32_t dst = sbase + (uint32_t)(18432 + buf * 36864 + arr * 9216 + row * ASTR + ch * 8) * 2;
        cp16(dst, src);
    }
}

__global__ __launch_bounds__(512, 1)
void attn_mma()
{
    extern __shared__ __nv_bfloat16 asm_sm[];
    const uint32_t sbase = smem_to_u32(asm_sm);
    float* pbuf = (float*)((char*)asm_sm + PBUF_B);   // [2: max/sum][2: side][128]

    const int qb   = gridDim.x - 1 - blockIdx.x;    // reversed: long CTAs first
    const int h    = blockIdx.y;
    const int hoff = h * HDIM;
    const int tid  = threadIdx.x;
    const int wid  = tid >> 5;
    const int lane = tid & 31;
    const int wp   = wid & 7;          // row-group
    const int side = wid >> 3;         // 0: cols 0..63, 1: cols 64..127
    const int lr4  = lane >> 2;
    const int kq   = lane & 3;

    // Q load (cp.async): 2048 chunks over 512 threads
#pragma unroll
    for (int i = 0; i < 4; i++) {
        int id  = tid + 512 * i;
        int arr = id >> 10;
        int rem = id & 1023;
        int row = rem >> 3;
        int ch  = rem & 7;
        const __nv_bfloat16* src = (arr ? g_ql : g_qh)
            + (size_t)(qb * 128 + row) * DM + hoff + ch * 8;
        uint32_t dst = sbase + (uint32_t)(arr * 9216 + row * ASTR + ch * 8) * 2;
        cp16(dst, src);
    }
    kv_load(sbase, tid, 0, 0, hoff);
    CP_COMMIT();

    const uint32_t qoff = (uint32_t)((wp * 16 + (lane & 7) + ((lane >> 3) & 1) * 8) * ASTR
                                     + ((lane >> 4) & 1) * 8);
    const uint32_t koff = (uint32_t)(((lane & 7) + ((lane >> 4) & 1) * 8) * ASTR
                                     + ((lane >> 3) & 1) * 8);
    const uint32_t voff = (uint32_t)(((lane & 7) + ((lane >> 3) & 1) * 8) * ASTR
                                     + ((lane >> 4) & 1) * 8);

    const int grow0 = wp * 16 + lr4;        // local row ids within 128-block
    const int grow1 = grow0 + 8;
    const int barid = 1 + wp;

    float o[8][4];
#pragma unroll
    for (int i = 0; i < 8; i++)
#pragma unroll
        for (int e = 0; e < 4; e++) o[i][e] = 0.f;
    float m_lo = -1e30f, m_hi = -1e30f, l_lo = 0.f, l_hi = 0.f;

    for (int kb = 0; kb <= qb; kb++) {
        const int buf = kb & 1;
        if (kb < qb) {
            kv_load(sbase, tid, kb + 1, buf ^ 1, hoff);
            CP_COMMIT();
            CP_WAIT1();
        } else {
            CP_WAIT0();
        }
        __syncthreads();

        const uint32_t Qh_b = sbase;
        const uint32_t Ql_b = sbase + 9216 * 2;
        const uint32_t Kh_b = sbase + (uint32_t)(18432 + buf * 36864) * 2;
        const uint32_t Kl_b = Kh_b + 9216 * 2;
        const uint32_t Vh_b = Kh_b + 2 * 9216 * 2;
        const uint32_t Vl_b = Kh_b + 3 * 9216 * 2;

        // ---- S = Q K^T (this warp: 16 rows x 64 cols of its side) ----
        float s[8][4];
#pragma unroll
        for (int j = 0; j < 8; j++)
#pragma unroll
            for (int e = 0; e < 4; e++) s[j][e] = 0.f;

#pragma unroll
        for (int ks = 0; ks < 4; ks++) {
            uint32_t ah[4], al[4];
            ldsm4(ah, Qh_b + (qoff + ks * 16) * 2);
            ldsm4(al, Ql_b + (qoff + ks * 16) * 2);
#pragma unroll
            for (int jp = 0; jp < 4; jp++) {
                uint32_t bh[4], bl[4];
                const uint32_t kb_off = (koff + (uint32_t)((side * 64 + jp * 16) * ASTR) + ks * 16) * 2;
                ldsm4(bh, Kh_b + kb_off);
                ldsm4(bl, Kl_b + kb_off);
                mma16816(s[2 * jp],     ah, bh);
                mma16816(s[2 * jp],     ah, bl);
                mma16816(s[2 * jp],     al, bh);
                mma16816(s[2 * jp + 1], ah, bh + 2);
                mma16816(s[2 * jp + 1], ah, bl + 2);
                mma16816(s[2 * jp + 1], al, bh + 2);
            }
        }

        // ---- causal mask (diag block only) ----
        if (kb == qb) {
            const int rl = wp * 16 + lr4;
#pragma unroll
            for (int j = 0; j < 8; j++) {
                int c0 = side * 64 + j * 8 + kq * 2;
                if (c0     > rl)     s[j][0] = -1e30f;
                if (c0 + 1 > rl)     s[j][1] = -1e30f;
                if (c0     > rl + 8) s[j][2] = -1e30f;
                if (c0 + 1 > rl + 8) s[j][3] = -1e30f;
            }
        }

        // ---- online softmax with pair exchange ----
        float bm_lo = -1e30f, bm_hi = -1e30f;
#pragma unroll
        for (int j = 0; j < 8; j++) {
            bm_lo = fmaxf(bm_lo, fmaxf(s[j][0], s[j][1]));
            bm_hi = fmaxf(bm_hi, fmaxf(s[j][2], s[j][3]));
        }
#pragma unroll
        for (int off = 1; off <= 2; off <<= 1) {
            bm_lo = fmaxf(bm_lo, __shfl_xor_sync(0xffffffffu, bm_lo, off));
            bm_hi = fmaxf(bm_hi, __shfl_xor_sync(0xffffffffu, bm_hi, off));
        }
        if (kq == 0) {
            pbuf[side * 128 + grow0] = bm_lo;
            pbuf[side * 128 + grow1] = bm_hi;
        }
        PAIR_BAR(barid);
        bm_lo = fmaxf(bm_lo, pbuf[(side ^ 1) * 128 + grow0]);
        bm_hi = fmaxf(bm_hi, pbuf[(side ^ 1) * 128 + grow1]);

        const float mn_lo = fmaxf(m_lo, bm_lo);
        const float mn_hi = fmaxf(m_hi, bm_hi);
        const float cor_lo = __expf(m_lo - mn_lo);
        const float cor_hi = __expf(m_hi - mn_hi);
        m_lo = mn_lo; m_hi = mn_hi;

        float sum_lo = 0.f, sum_hi = 0.f;
#pragma unroll
        for (int j = 0; j < 8; j++) {
            s[j][0] = __expf(s[j][0] - mn_lo);
            s[j][1] = __expf(s[j][1] - mn_lo);
            s[j][2] = __expf(s[j][2] - mn_hi);
            s[j][3] = __expf(s[j][3] - mn_hi);
            sum_lo += s[j][0] + s[j][1];
            sum_hi += s[j][2] + s[j][3];
        }
#pragma unroll
        for (int off = 1; off <= 2; off <<= 1) {
            sum_lo += __shfl_xor_sync(0xffffffffu, sum_lo, off);
            sum_hi += __shfl_xor_sync(0xffffffffu, sum_hi, off);
        }
        if (kq == 0) {
            pbuf[256 + side * 128 + grow0] = sum_lo;
            pbuf[256 + side * 128 + grow1] = sum_hi;
        }
        PAIR_BAR(barid);
        sum_lo += pbuf[256 + (side ^ 1) * 128 + grow0];
        sum_hi += pbuf[256 + (side ^ 1) * 128 + grow1];

        l_lo = l_lo * cor_lo + sum_lo;
        l_hi = l_hi * cor_hi + sum_hi;
#pragma unroll
        for (int j2 = 0; j2 < 8; j2++) {
            o[j2][0] *= cor_lo; o[j2][1] *= cor_lo;
            o[j2][2] *= cor_hi; o[j2][3] *= cor_hi;
        }

        // ---- O += P V (this warp: KV rows side*64 .. +63, all 64 d) ----
#pragma unroll
        for (int ks2 = 0; ks2 < 4; ks2++) {
            const int j0 = 2 * ks2, j1 = 2 * ks2 + 1;
            uint32_t ph[4], pl[4];
#pragma unroll
            for (int q4 = 0; q4 < 4; q4++) {
                const float p0 = (q4 < 2) ? s[j0][(q4 & 1) * 2]     : s[j1][(q4 & 1) * 2];
                const float p1 = (q4 < 2) ? s[j0][(q4 & 1) * 2 + 1] : s[j1][(q4 & 1) * 2 + 1];
                uint32_t hp = packbf(p0, p1);
                __nv_bfloat162 hb = *(__nv_bfloat162*)&hp;
                float r0 = p0 - __bfloat162float(hb.x);
                float r1 = p1 - __bfloat162float(hb.y);
                ph[q4] = hp;
                pl[q4] = packbf(r0, r1);
            }
#pragma unroll
            for (int jp2 = 0; jp2 < 4; jp2++) {
                uint32_t vh[4], vl[4];
                const uint32_t vb_off = (voff + (uint32_t)((side * 64 + ks2 * 16) * ASTR) + jp2 * 16) * 2;
                ldsm4t(vh, Vh_b + vb_off);
                ldsm4t(vl, Vl_b + vb_off);
                mma16816(o[2 * jp2],     ph, vh);
                mma16816(o[2 * jp2],     ph, vl);
                mma16816(o[2 * jp2],     pl, vh);
                mma16816(o[2 * jp2 + 1], ph, vh + 2);
                mma16816(o[2 * jp2 + 1], ph, vl + 2);
                mma16816(o[2 * jp2 + 1], pl, vh + 2);
            }
        }
        __syncthreads();   // done reading buf before next-iter cp.async overwrites it
    }

    // ---- epilogue: combine O partials across pair, normalize, split, write ----
    // exchange buffer reuses KV region: per wp 4KB: [16 rows][64 cols] fp32
    float* exch = (float*)((char*)asm_sm + 18432 * 2) + wp * 1024;
    if (side == 1) {
#pragma unroll
        for (int j2 = 0; j2 < 8; j2++) {
            const int col = j2 * 8 + kq * 2;
            *(float2*)&exch[lr4 * 64 + col]       = make_float2(o[j2][0], o[j2][1]);
            *(float2*)&exch[(lr4 + 8) * 64 + col] = make_float2(o[j2][2], o[j2][3]);
        }
    }
    __syncthreads();
    if (side == 0) {
        const float inv_lo = 1.0f / l_lo;
        const float inv_hi = 1.0f / l_hi;
        const int row_g = qb * 128 + wp * 16 + lr4;
#pragma unroll
        for (int j2 = 0; j2 < 8; j2++) {
            const int col = hoff + j2 * 8 + kq * 2;
            float2 e0 = *(float2*)&exch[lr4 * 64 + j2 * 8 + kq * 2];
            float2 e1 = *(float2*)&exch[(lr4 + 8) * 64 + j2 * 8 + kq * 2];
            {
                float v0 = (o[j2][0] + e0.x) * inv_lo, v1 = (o[j2][1] + e0.y) * inv_lo;
                __nv_bfloat16 h0 = __float2bfloat16(v0);
                __nv_bfloat16 h1 = __float2bfloat16(v1);
                __nv_bfloat16 l0 = __float2bfloat16(v0 - __bfloat162float(h0));
                __nv_bfloat16 l1 = __float2bfloat16(v1 - __bfloat162float(h1));
                *(__nv_bfloat162*)&g_ch[(size_t)row_g * DM + col] = __halves2bfloat162(h0, h1);
                *(__nv_bfloat162*)&g_cl[(size_t)row_g * DM + col] = __halves2bfloat162(l0, l1);
            }
            {
                float v0 = (o[j2][2] + e1.x) * inv_hi, v1 = (o[j2][3] + e1.y) * inv_hi;
                __nv_bfloat16 h0 = __float2bfloat16(v0);
                __nv_bfloat16 h1 = __float2bfloat16(v1);
                __nv_bfloat16 l0 = __float2bfloat16(v0 - __bfloat162float(h0));
                __nv_bfloat16 l1 = __float2bfloat16(v1 - __bfloat162float(h1));
                *(__nv_bfloat162*)&g_ch[(size_t)(row_g + 8) * DM + col] = __halves2bfloat162(h0, h1);
                *(__nv_bfloat162*)&g_cl[(size_t)(row_g + 8) * DM + col] = __halves2bfloat162(l0, l1);
            }
        }
    }
}

// ---------------------------------------------------------------------------
extern "C" void kernel_launch(void* const* d_in, const int* in_sizes, int n_in,
                              void* d_out, int out_size)
{
    const float* x  = (const float*)d_in[0];
    const float* Wq = (const float*)d_in[1];
    const float* Wk = (const float*)d_in[2];
    const float* Wv = (const float*)d_in[3];
    const float* Wo = (const float*)d_in[4];
    const float* bo = (const float*)d_in[5];
    float* out = (float*)d_out;

    cudaFuncSetAttribute(tc_gemm, cudaFuncAttributeMaxDynamicSharedMemorySize, TCG_SMEM);
    cudaFuncSetAttribute(attn_mma, cudaFuncAttributeMaxDynamicSharedMemorySize, ATTN_SMEM);

    const int n2x = SQ * DM / 2;
    const int n2w = DM * DM / 2;

    split_x<<<n2x / 256, 256>>>(x, n2x);
    split_w<<<dim3(n2w / 256, 4), 256>>>(Wq, Wk, Wv, Wo, n2w);

    tc_gemm<<<dim3(DM / 128, SQ / 128, 3), 256, TCG_SMEM>>>(0, 0, 0, nullptr, nullptr);  // QKV

    attn_mma<<<dim3(SQ / 128, NH), 512, ATTN_SMEM>>>();

    tc_gemm<<<dim3(DM / 128, SQ / 128, 1), 256, TCG_SMEM>>>(1, 3, 3, out, bo);           // out proj
}

// round 13
// speedup vs baseline: 1.0748x; 1.0748x over previous
#include <cuda_runtime.h>
#include <cuda_bf16.h>
#include <cstdint>

// Problem constants
#define SQ   4096
#define DM   1024
#define NH   16
#define HDIM 64

// ---------------------------------------------------------------------------
// Scratch (allocation-free rule: __device__ globals) — all bf16 hi/lo pairs
// ---------------------------------------------------------------------------
__device__ __align__(16) __nv_bfloat16 g_xh[SQ * DM];
__device__ __align__(16) __nv_bfloat16 g_xl[SQ * DM];
__device__ __align__(16) __nv_bfloat16 g_wh[4][DM * DM];
__device__ __align__(16) __nv_bfloat16 g_wl[4][DM * DM];
__device__ __align__(16) __nv_bfloat16 g_qh[SQ * DM];   // pre-scaled by 0.125
__device__ __align__(16) __nv_bfloat16 g_ql[SQ * DM];
__device__ __align__(16) __nv_bfloat16 g_kh[SQ * DM];
__device__ __align__(16) __nv_bfloat16 g_kl[SQ * DM];
__device__ __align__(16) __nv_bfloat16 g_vh[SQ * DM];
__device__ __align__(16) __nv_bfloat16 g_vl[SQ * DM];
__device__ __align__(16) __nv_bfloat16 g_ch[SQ * DM];
__device__ __align__(16) __nv_bfloat16 g_cl[SQ * DM];

// ---------------------------------------------------------------------------
// PTX helpers (legacy / non-'a' instructions only: HMMA, ldmatrix, cp.async)
// ---------------------------------------------------------------------------
__device__ __forceinline__ uint32_t smem_to_u32(const void* p) {
    uint32_t a;
    asm("{ .reg .u64 t; cvta.to.shared.u64 t, %1; cvt.u32.u64 %0, t; }"
        : "=r"(a) : "l"(p));
    return a;
}

__device__ __forceinline__ void mma16816(float* c, const uint32_t* a, const uint32_t* b)
{
    asm volatile(
        "mma.sync.aligned.m16n8k16.row.col.f32.bf16.bf16.f32 "
        "{%0,%1,%2,%3}, {%4,%5,%6,%7}, {%8,%9}, {%0,%1,%2,%3};\n"
        : "+f"(c[0]), "+f"(c[1]), "+f"(c[2]), "+f"(c[3])
        : "r"(a[0]), "r"(a[1]), "r"(a[2]), "r"(a[3]), "r"(b[0]), "r"(b[1]));
}

__device__ __forceinline__ void ldsm4(uint32_t* r, uint32_t addr)
{
    asm volatile("ldmatrix.sync.aligned.m8n8.x4.shared.b16 {%0,%1,%2,%3}, [%4];"
        : "=r"(r[0]), "=r"(r[1]), "=r"(r[2]), "=r"(r[3]) : "r"(addr));
}

__device__ __forceinline__ void ldsm4t(uint32_t* r, uint32_t addr)
{
    asm volatile("ldmatrix.sync.aligned.m8n8.x4.trans.shared.b16 {%0,%1,%2,%3}, [%4];"
        : "=r"(r[0]), "=r"(r[1]), "=r"(r[2]), "=r"(r[3]) : "r"(addr));
}

__device__ __forceinline__ void cp16(uint32_t dst, const void* src)
{
    asm volatile("cp.async.ca.shared.global [%0], [%1], 16;" :: "r"(dst), "l"(src));
}
#define CP_COMMIT() asm volatile("cp.async.commit_group;" ::: "memory")
#define CP_WAIT0()  asm volatile("cp.async.wait_group 0;" ::: "memory")
#define CP_WAIT1()  asm volatile("cp.async.wait_group 1;" ::: "memory")

__device__ __forceinline__ uint32_t packbf(float lo, float hi)
{
    uint32_t r;
    asm("cvt.rn.bf16x2.f32 %0, %1, %2;" : "=r"(r) : "f"(hi), "f"(lo));
    return r;
}

// ---------------------------------------------------------------------------
// fp32 -> bf16 hi/lo splitters
// ---------------------------------------------------------------------------
__device__ __forceinline__ void split_pair(const float2 v, __nv_bfloat16* hi,
                                           __nv_bfloat16* lo, int i)
{
    __nv_bfloat16 h0 = __float2bfloat16(v.x);
    __nv_bfloat16 h1 = __float2bfloat16(v.y);
    __nv_bfloat16 l0 = __float2bfloat16(v.x - __bfloat162float(h0));
    __nv_bfloat16 l1 = __float2bfloat16(v.y - __bfloat162float(h1));
    ((__nv_bfloat162*)hi)[i] = __halves2bfloat162(h0, h1);
    ((__nv_bfloat162*)lo)[i] = __halves2bfloat162(l0, l1);
}

__global__ void split_x(const float* __restrict__ src, int n2)
{
    int i = blockIdx.x * blockDim.x + threadIdx.x;
    if (i >= n2) return;
    split_pair(((const float2*)src)[i], g_xh, g_xl, i);
}

__global__ void split_w(const float* __restrict__ w0, const float* __restrict__ w1,
                        const float* __restrict__ w2, const float* __restrict__ w3,
                        int n2)
{
    int wi = blockIdx.y;
    const float* src = (wi == 0) ? w0 : (wi == 1) ? w1 : (wi == 2) ? w2 : w3;
    int i = blockIdx.x * blockDim.x + threadIdx.x;
    if (i >= n2) return;
    split_pair(((const float2*)src)[i], g_wh[wi], g_wl[wi], i);
}

// ---------------------------------------------------------------------------
// HMMA GEMM: C[4096,1024] = A[4096,1024] * B[1024,1024]^T
// 2-stage cp.async, 2 CTAs/SM (smem 80KB, regs capped by launch_bounds(256,2)).
// BK=32 per iteration (2 k16 halves).   [R12 measured version — kept]
// ---------------------------------------------------------------------------
#define GSTR 40
#define GARR (128 * GSTR)              // 5120 bf16 = 10240 B
#define NSTG 2
#define TCG_SMEM (int)(NSTG * 4 * GARR * sizeof(__nv_bfloat16))   // 81920 B

__global__ __launch_bounds__(256, 2)
void tc_gemm(int asel, int wsel, int csel, float* Cparam, const float* bias)
{
    extern __shared__ __nv_bfloat16 smem[];
    const uint32_t sbase = smem_to_u32(smem);

    if (gridDim.z == 3) { wsel = blockIdx.z; csel = blockIdx.z; }

    const __nv_bfloat16* GAh = asel ? g_ch : g_xh;
    const __nv_bfloat16* GAl = asel ? g_cl : g_xl;
    const __nv_bfloat16* GBh = g_wh[wsel];
    const __nv_bfloat16* GBl = g_wl[wsel];

    const int tid  = threadIdx.x;
    const int wid  = tid >> 5;
    const int lane = tid & 31;
    const int wm   = wid >> 2;
    const int wn   = wid & 3;
    const int lr4  = lane >> 2;
    const int kq   = lane & 3;
    const int m0   = blockIdx.y * 128;
    const int n0   = blockIdx.x * 128;

    const int lrow0 = tid >> 2;
    const int lch   = tid & 3;
    const uint32_t sd0 = (uint32_t)(lrow0 * GSTR + lch * 8) * 2;
    const uint32_t sd1 = (uint32_t)((lrow0 + 64) * GSTR + lch * 8) * 2;

    const uint32_t aoff = (uint32_t)((wm * 64 + (lane & 15)) * GSTR + ((lane >> 4) & 1) * 8) * 2;
    const uint32_t boff = (uint32_t)((wn * 32 + (lane & 7) + ((lane >> 4) & 1) * 8) * GSTR
                                     + ((lane >> 3) & 1) * 8) * 2;

    float c[4][4][4];
#pragma unroll
    for (int i = 0; i < 4; i++)
#pragma unroll
        for (int j = 0; j < 4; j++)
#pragma unroll
            for (int e = 0; e < 4; e++) c[i][j][e] = 0.f;

#define ISSUE_STAGE(t) do { \
        uint32_t sb_ = sbase + (uint32_t)(((t) % NSTG) * 4 * GARR) * 2; \
        size_t koA0_ = (size_t)(m0 + lrow0) * DM + (size_t)(t) * 32 + lch * 8; \
        size_t koA1_ = (size_t)(m0 + lrow0 + 64) * DM + (size_t)(t) * 32 + lch * 8; \
        size_t koB0_ = (size_t)(n0 + lrow0) * DM + (size_t)(t) * 32 + lch * 8; \
        size_t koB1_ = (size_t)(n0 + lrow0 + 64) * DM + (size_t)(t) * 32 + lch * 8; \
        cp16(sb_ + sd0,                GAh + koA0_); \
        cp16(sb_ + sd1,                GAh + koA1_); \
        cp16(sb_ + GARR * 2 + sd0,     GAl + koA0_); \
        cp16(sb_ + GARR * 2 + sd1,     GAl + koA1_); \
        cp16(sb_ + 2 * GARR * 2 + sd0, GBh + koB0_); \
        cp16(sb_ + 2 * GARR * 2 + sd1, GBh + koB1_); \
        cp16(sb_ + 3 * GARR * 2 + sd0, GBl + koB0_); \
        cp16(sb_ + 3 * GARR * 2 + sd1, GBl + koB1_); \
        CP_COMMIT(); \
    } while (0)

    ISSUE_STAGE(0);
    ISSUE_STAGE(1);

    for (int t = 0; t < 32; t++) {
        if (t == 31) CP_WAIT0(); else CP_WAIT1();
        __syncthreads();

        const uint32_t stg = sbase + (uint32_t)((t % NSTG) * 4 * GARR) * 2;

#pragma unroll
        for (int kh = 0; kh < 2; kh++) {
            const uint32_t ko = (uint32_t)(kh * 16) * 2;
            uint32_t ah[4][4], al[4][4], bh[2][4], bl[2][4];
#pragma unroll
            for (int i = 0; i < 4; i++) {
                ldsm4(ah[i], stg + aoff + ko + (uint32_t)(i * 16 * GSTR) * 2);
                ldsm4(al[i], stg + GARR * 2 + aoff + ko + (uint32_t)(i * 16 * GSTR) * 2);
            }
#pragma unroll
            for (int jj = 0; jj < 2; jj++) {
                ldsm4(bh[jj], stg + 2 * GARR * 2 + boff + ko + (uint32_t)(jj * 16 * GSTR) * 2);
                ldsm4(bl[jj], stg + 3 * GARR * 2 + boff + ko + (uint32_t)(jj * 16 * GSTR) * 2);
            }

#pragma unroll
            for (int i = 0; i < 4; i++)
#pragma unroll
                for (int j = 0; j < 4; j++) {
                    const uint32_t* fh = bh[j >> 1] + (j & 1) * 2;
                    const uint32_t* fl = bl[j >> 1] + (j & 1) * 2;
                    mma16816(c[i][j], ah[i], fh);
                    mma16816(c[i][j], ah[i], fl);
                    mma16816(c[i][j], al[i], fh);
                }
        }

        __syncthreads();                  // all warps done with slot t%2
        if (t + 2 < 32) ISSUE_STAGE(t + 2);
    }
#undef ISSUE_STAGE

    if (csel < 3) {
        __nv_bfloat16* Hd = (csel == 0) ? g_qh : (csel == 1) ? g_kh : g_vh;
        __nv_bfloat16* Ld = (csel == 0) ? g_ql : (csel == 1) ? g_kl : g_vl;
        const float scale = (csel == 0) ? 0.125f : 1.0f;
#pragma unroll
        for (int i = 0; i < 4; i++) {
            int r = m0 + wm * 64 + i * 16 + lr4;
#pragma unroll
            for (int j = 0; j < 4; j++) {
                int col = n0 + wn * 32 + j * 8 + kq * 2;
#pragma unroll
                for (int half = 0; half < 2; half++) {
                    int rr = r + half * 8;
                    float v0 = c[i][j][half * 2 + 0] * scale;
                    float v1 = c[i][j][half * 2 + 1] * scale;
                    __nv_bfloat16 h0 = __float2bfloat16(v0);
                    __nv_bfloat16 h1 = __float2bfloat16(v1);
                    __nv_bfloat16 l0 = __float2bfloat16(v0 - __bfloat162float(h0));
                    __nv_bfloat16 l1 = __float2bfloat16(v1 - __bfloat162float(h1));
                    *(__nv_bfloat162*)&Hd[(size_t)rr * DM + col] = __halves2bfloat162(h0, h1);
                    *(__nv_bfloat162*)&Ld[(size_t)rr * DM + col] = __halves2bfloat162(l0, l1);
                }
            }
        }
    } else {
#pragma unroll
        for (int i = 0; i < 4; i++) {
            int r = m0 + wm * 64 + i * 16 + lr4;
#pragma unroll
            for (int j = 0; j < 4; j++) {
                int col = n0 + wn * 32 + j * 8 + kq * 2;
                float bx = bias[col], by = bias[col + 1];
                *(float2*)(Cparam + (size_t)r * DM + col)       = make_float2(c[i][j][0] + bx, c[i][j][1] + by);
                *(float2*)(Cparam + (size_t)(r + 8) * DM + col) = make_float2(c[i][j][2] + bx, c[i][j][3] + by);
            }
        }
    }
}

// ---------------------------------------------------------------------------
// MMA flash attention, causal — byte-identical to the R11 measured version
// (256 threads, 8 independent warps x 16 rows, 355us @ tensor 49%).
// ---------------------------------------------------------------------------
#define ASTR 72
#define ATILE (128 * ASTR)              // 9216 bf16
#define ATTN_SMEM (int)((2 * ATILE + 2 * 4 * ATILE) * sizeof(__nv_bfloat16))  // 184320 B

__device__ __forceinline__ void kv_load(uint32_t sbase, int tid, int kb, int buf, int hoff)
{
#pragma unroll
    for (int i = 0; i < 16; i++) {
        int id  = tid + 256 * i;
        int arr = id >> 10;
        int rem = id & 1023;
        int row = rem >> 3;
        int ch  = rem & 7;
        const __nv_bfloat16* src =
            ((arr == 0) ? g_kh : (arr == 1) ? g_kl : (arr == 2) ? g_vh : g_vl)
            + (size_t)(kb * 128 + row) * DM + hoff + ch * 8;
        uint32_t dst = sbase + (uint32_t)(18432 + buf * 36864 + arr * 9216 + row * ASTR + ch * 8) * 2;
        cp16(dst, src);
    }
}

__global__ __launch_bounds__(256, 1)
void attn_mma()
{
    extern __shared__ __nv_bfloat16 asm_sm[];
    const uint32_t sbase = smem_to_u32(asm_sm);

    const int qb   = gridDim.x - 1 - blockIdx.x;    // reversed: long CTAs first
    const int h    = blockIdx.y;
    const int hoff = h * HDIM;
    const int tid  = threadIdx.x;
    const int wid  = tid >> 5;
    const int lane = tid & 31;
    const int lr4  = lane >> 2;
    const int kq   = lane & 3;

    // Q load (cp.async)
#pragma unroll
    for (int i = 0; i < 8; i++) {
        int id  = tid + 256 * i;
        int arr = id >> 10;
        int rem = id & 1023;
        int row = rem >> 3;
        int ch  = rem & 7;
        const __nv_bfloat16* src = (arr ? g_ql : g_qh)
            + (size_t)(qb * 128 + row) * DM + hoff + ch * 8;
        uint32_t dst = sbase + (uint32_t)(arr * 9216 + row * ASTR + ch * 8) * 2;
        cp16(dst, src);
    }
    kv_load(sbase, tid, 0, 0, hoff);
    CP_COMMIT();

    const uint32_t qoff = (uint32_t)((wid * 16 + (lane & 7) + ((lane >> 3) & 1) * 8) * ASTR
                                     + ((lane >> 4) & 1) * 8);
    const uint32_t koff = (uint32_t)(((lane & 7) + ((lane >> 4) & 1) * 8) * ASTR
                                     + ((lane >> 3) & 1) * 8);
    const uint32_t voff = (uint32_t)(((lane & 7) + ((lane >> 3) & 1) * 8) * ASTR
                                     + ((lane >> 4) & 1) * 8);

    float o[8][4];
#pragma unroll
    for (int i = 0; i < 8; i++)
#pragma unroll
        for (int e = 0; e < 4; e++) o[i][e] = 0.f;
    float m_lo = -1e30f, m_hi = -1e30f, l_lo = 0.f, l_hi = 0.f;

    for (int kb = 0; kb <= qb; kb++) {
        const int buf = kb & 1;
        if (kb < qb) {
            kv_load(sbase, tid, kb + 1, buf ^ 1, hoff);
            CP_COMMIT();
            CP_WAIT1();
        } else {
            CP_WAIT0();
        }
        __syncthreads();

        const uint32_t Qh_b = sbase;
        const uint32_t Ql_b = sbase + 9216 * 2;
        const uint32_t Kh_b = sbase + (uint32_t)(18432 + buf * 36864) * 2;
        const uint32_t Kl_b = Kh_b + 9216 * 2;
        const uint32_t Vh_b = Kh_b + 2 * 9216 * 2;
        const uint32_t Vl_b = Kh_b + 3 * 9216 * 2;

        // ---- S = Q K^T ----
        float s[16][4];
#pragma unroll
        for (int j = 0; j < 16; j++)
#pragma unroll
            for (int e = 0; e < 4; e++) s[j][e] = 0.f;

#pragma unroll
        for (int ks = 0; ks < 4; ks++) {
            uint32_t ah[4], al[4];
            ldsm4(ah, Qh_b + (qoff + ks * 16) * 2);
            ldsm4(al, Ql_b + (qoff + ks * 16) * 2);
#pragma unroll
            for (int jp = 0; jp < 8; jp++) {
                uint32_t bh[4], bl[4];
                ldsm4(bh, Kh_b + (koff + jp * 16 * ASTR + ks * 16) * 2);
                ldsm4(bl, Kl_b + (koff + jp * 16 * ASTR + ks * 16) * 2);
                mma16816(s[2 * jp],     ah, bh);
                mma16816(s[2 * jp],     ah, bl);
                mma16816(s[2 * jp],     al, bh);
                mma16816(s[2 * jp + 1], ah, bh + 2);
                mma16816(s[2 * jp + 1], ah, bl + 2);
                mma16816(s[2 * jp + 1], al, bh + 2);
            }
        }

        // ---- causal mask (diag block only) ----
        if (kb == qb) {
            const int rl = wid * 16 + lr4;
#pragma unroll
            for (int j = 0; j < 16; j++) {
                int c0 = j * 8 + kq * 2;
                if (c0     > rl)     s[j][0] = -1e30f;
                if (c0 + 1 > rl)     s[j][1] = -1e30f;
                if (c0     > rl + 8) s[j][2] = -1e30f;
                if (c0 + 1 > rl + 8) s[j][3] = -1e30f;
            }
        }

        // ---- online softmax ----
        float bm_lo = -1e30f, bm_hi = -1e30f;
#pragma unroll
        for (int j = 0; j < 16; j++) {
            bm_lo = fmaxf(bm_lo, fmaxf(s[j][0], s[j][1]));
            bm_hi = fmaxf(bm_hi, fmaxf(s[j][2], s[j][3]));
        }
#pragma unroll
        for (int off = 1; off <= 2; off <<= 1) {
            bm_lo = fmaxf(bm_lo, __shfl_xor_sync(0xffffffffu, bm_lo, off));
            bm_hi = fmaxf(bm_hi, __shfl_xor_sync(0xffffffffu, bm_hi, off));
        }
        const float mn_lo = fmaxf(m_lo, bm_lo);
        const float mn_hi = fmaxf(m_hi, bm_hi);
        const float cor_lo = __expf(m_lo - mn_lo);
        const float cor_hi = __expf(m_hi - mn_hi);
        m_lo = mn_lo; m_hi = mn_hi;

        float sum_lo = 0.f, sum_hi = 0.f;
#pragma unroll
        for (int j = 0; j < 16; j++) {
            s[j][0] = __expf(s[j][0] - mn_lo);
            s[j][1] = __expf(s[j][1] - mn_lo);
            s[j][2] = __expf(s[j][2] - mn_hi);
            s[j][3] = __expf(s[j][3] - mn_hi);
            sum_lo += s[j][0] + s[j][1];
            sum_hi += s[j][2] + s[j][3];
        }
#pragma unroll
        for (int off = 1; off <= 2; off <<= 1) {
            sum_lo += __shfl_xor_sync(0xffffffffu, sum_lo, off);
            sum_hi += __shfl_xor_sync(0xffffffffu, sum_hi, off);
        }
        l_lo = l_lo * cor_lo + sum_lo;
        l_hi = l_hi * cor_hi + sum_hi;
#pragma unroll
        for (int j2 = 0; j2 < 8; j2++) {
            o[j2][0] *= cor_lo; o[j2][1] *= cor_lo;
            o[j2][2] *= cor_hi; o[j2][3] *= cor_hi;
        }

        // ---- O += P V ----
#pragma unroll
        for (int ks2 = 0; ks2 < 8; ks2++) {
            const int j0 = 2 * ks2, j1 = 2 * ks2 + 1;
            uint32_t ph[4], pl[4];
#pragma unroll
            for (int q4 = 0; q4 < 4; q4++) {
                const float p0 = (q4 < 2) ? s[j0][(q4 & 1) * 2]     : s[j1][(q4 & 1) * 2];
                const float p1 = (q4 < 2) ? s[j0][(q4 & 1) * 2 + 1] : s[j1][(q4 & 1) * 2 + 1];
                uint32_t hp = packbf(p0, p1);
                __nv_bfloat162 hb = *(__nv_bfloat162*)&hp;
                float r0 = p0 - __bfloat162float(hb.x);
                float r1 = p1 - __bfloat162float(hb.y);
                ph[q4] = hp;
                pl[q4] = packbf(r0, r1);
            }
#pragma unroll
            for (int jp2 = 0; jp2 < 4; jp2++) {
                uint32_t vh[4], vl[4];
                ldsm4t(vh, Vh_b + (voff + ks2 * 16 * ASTR + jp2 * 16) * 2);
                ldsm4t(vl, Vl_b + (voff + ks2 * 16 * ASTR + jp2 * 16) * 2);
                mma16816(o[2 * jp2],     ph, vh);
                mma16816(o[2 * jp2],     ph, vl);
                mma16816(o[2 * jp2],     pl, vh);
                mma16816(o[2 * jp2 + 1], ph, vh + 2);
                mma16816(o[2 * jp2 + 1], ph, vl + 2);
                mma16816(o[2 * jp2 + 1], pl, vh + 2);
            }
        }
        __syncthreads();
    }

    // ---- epilogue ----
    const float inv_lo = 1.0f / l_lo;
    const float inv_hi = 1.0f / l_hi;
    const int row_g = qb * 128 + wid * 16 + lr4;
#pragma unroll
    for (int j2 = 0; j2 < 8; j2++) {
        const int col = hoff + j2 * 8 + kq * 2;
        {
            float v0 = o[j2][0] * inv_lo, v1 = o[j2][1] * inv_lo;
            __nv_bfloat16 h0 = __float2bfloat16(v0);
            __nv_bfloat16 h1 = __float2bfloat16(v1);
            __nv_bfloat16 l0 = __float2bfloat16(v0 - __bfloat162float(h0));
            __nv_bfloat16 l1 = __float2bfloat16(v1 - __bfloat162float(h1));
            *(__nv_bfloat162*)&g_ch[(size_t)row_g * DM + col] = __halves2bfloat162(h0, h1);
            *(__nv_bfloat162*)&g_cl[(size_t)row_g * DM + col] = __halves2bfloat162(l0, l1);
        }
        {
            float v0 = o[j2][2] * inv_hi, v1 = o[j2][3] * inv_hi;
            __nv_bfloat16 h0 = __float2bfloat16(v0);
            __nv_bfloat16 h1 = __float2bfloat16(v1);
            __nv_bfloat16 l0 = __float2bfloat16(v0 - __bfloat162float(h0));
            __nv_bfloat16 l1 = __float2bfloat16(v1 - __bfloat162float(h1));
            *(__nv_bfloat162*)&g_ch[(size_t)(row_g + 8) * DM + col] = __halves2bfloat162(h0, h1);
            *(__nv_bfloat162*)&g_cl[(size_t)(row_g + 8) * DM + col] = __halves2bfloat162(l0, l1);
        }
    }
}

// ---------------------------------------------------------------------------
extern "C" void kernel_launch(void* const* d_in, const int* in_sizes, int n_in,
                              void* d_out, int out_size)
{
    const float* x  = (const float*)d_in[0];
    const float* Wq = (const float*)d_in[1];
    const float* Wk = (const float*)d_in[2];
    const float* Wv = (const float*)d_in[3];
    const float* Wo = (const float*)d_in[4];
    const float* bo = (const float*)d_in[5];
    float* out = (float*)d_out;

    cudaFuncSetAttribute(tc_gemm, cudaFuncAttributeMaxDynamicSharedMemorySize, TCG_SMEM);
    cudaFuncSetAttribute(attn_mma, cudaFuncAttributeMaxDynamicSharedMemorySize, ATTN_SMEM);

    const int n2x = SQ * DM / 2;
    const int n2w = DM * DM / 2;

    split_x<<<n2x / 256, 256>>>(x, n2x);
    split_w<<<dim3(n2w / 256, 4), 256>>>(Wq, Wk, Wv, Wo, n2w);

    tc_gemm<<<dim3(DM / 128, SQ / 128, 3), 256, TCG_SMEM>>>(0, 0, 0, nullptr, nullptr);  // QKV

    attn_mma<<<dim3(SQ / 128, NH), 256, ATTN_SMEM>>>();

    tc_gemm<<<dim3(DM / 128, SQ / 128, 1), 256, TCG_SMEM>>>(1, 3, 3, out, bo);           // out proj
}

// round 17
// speedup vs baseline: 1.1025x; 1.0257x over previous
#include <cuda_runtime.h>
#include <cuda_bf16.h>
#include <cstdint>

// Problem constants
#define SQ   4096
#define DM   1024
#define NH   16
#define HDIM 64

// ---------------------------------------------------------------------------
// Scratch (allocation-free rule: __device__ globals) — all bf16 hi/lo pairs
// ---------------------------------------------------------------------------
__device__ __align__(16) __nv_bfloat16 g_xh[SQ * DM];
__device__ __align__(16) __nv_bfloat16 g_xl[SQ * DM];
__device__ __align__(16) __nv_bfloat16 g_wh[4][DM * DM];
__device__ __align__(16) __nv_bfloat16 g_wl[4][DM * DM];
__device__ __align__(16) __nv_bfloat16 g_qh[SQ * DM];   // pre-scaled by 0.125
__device__ __align__(16) __nv_bfloat16 g_ql[SQ * DM];
__device__ __align__(16) __nv_bfloat16 g_kh[SQ * DM];
__device__ __align__(16) __nv_bfloat16 g_kl[SQ * DM];
__device__ __align__(16) __nv_bfloat16 g_vh[SQ * DM];
__device__ __align__(16) __nv_bfloat16 g_vl[SQ * DM];
__device__ __align__(16) __nv_bfloat16 g_ch[SQ * DM];
__device__ __align__(16) __nv_bfloat16 g_cl[SQ * DM];

// ---------------------------------------------------------------------------
// PTX helpers (legacy / non-'a' instructions only: HMMA, ldmatrix, cp.async)
// ---------------------------------------------------------------------------
__device__ __forceinline__ uint32_t smem_to_u32(const void* p) {
    uint32_t a;
    asm("{ .reg .u64 t; cvta.to.shared.u64 t, %1; cvt.u32.u64 %0, t; }"
        : "=r"(a) : "l"(p));
    return a;
}

__device__ __forceinline__ void mma16816(float* c, const uint32_t* a, const uint32_t* b)
{
    asm volatile(
        "mma.sync.aligned.m16n8k16.row.col.f32.bf16.bf16.f32 "
        "{%0,%1,%2,%3}, {%4,%5,%6,%7}, {%8,%9}, {%0,%1,%2,%3};\n"
        : "+f"(c[0]), "+f"(c[1]), "+f"(c[2]), "+f"(c[3])
        : "r"(a[0]), "r"(a[1]), "r"(a[2]), "r"(a[3]), "r"(b[0]), "r"(b[1]));
}

__device__ __forceinline__ void ldsm4(uint32_t* r, uint32_t addr)
{
    asm volatile("ldmatrix.sync.aligned.m8n8.x4.shared.b16 {%0,%1,%2,%3}, [%4];"
        : "=r"(r[0]), "=r"(r[1]), "=r"(r[2]), "=r"(r[3]) : "r"(addr));
}

__device__ __forceinline__ void ldsm4t(uint32_t* r, uint32_t addr)
{
    asm volatile("ldmatrix.sync.aligned.m8n8.x4.trans.shared.b16 {%0,%1,%2,%3}, [%4];"
        : "=r"(r[0]), "=r"(r[1]), "=r"(r[2]), "=r"(r[3]) : "r"(addr));
}

__device__ __forceinline__ void cp16(uint32_t dst, const void* src)
{
    asm volatile("cp.async.ca.shared.global [%0], [%1], 16;" :: "r"(dst), "l"(src));
}
#define CP_COMMIT() asm volatile("cp.async.commit_group;" ::: "memory")
#define CP_WAIT0()  asm volatile("cp.async.wait_group 0;" ::: "memory")
#define CP_WAIT1()  asm volatile("cp.async.wait_group 1;" ::: "memory")

__device__ __forceinline__ uint32_t packbf(float lo, float hi)
{
    uint32_t r;
    asm("cvt.rn.bf16x2.f32 %0, %1, %2;" : "=r"(r) : "f"(hi), "f"(lo));
    return r;
}

// ---------------------------------------------------------------------------
// fp32 -> bf16 hi/lo splitters
// ---------------------------------------------------------------------------
__device__ __forceinline__ void split_pair(const float2 v, __nv_bfloat16* hi,
                                           __nv_bfloat16* lo, int i)
{
    __nv_bfloat16 h0 = __float2bfloat16(v.x);
    __nv_bfloat16 h1 = __float2bfloat16(v.y);
    __nv_bfloat16 l0 = __float2bfloat16(v.x - __bfloat162float(h0));
    __nv_bfloat16 l1 = __float2bfloat16(v.y - __bfloat162float(h1));
    ((__nv_bfloat162*)hi)[i] = __halves2bfloat162(h0, h1);
    ((__nv_bfloat162*)lo)[i] = __halves2bfloat162(l0, l1);
}

__global__ void split_x(const float* __restrict__ src, int n2)
{
    int i = blockIdx.x * blockDim.x + threadIdx.x;
    if (i >= n2) return;
    split_pair(((const float2*)src)[i], g_xh, g_xl, i);
}

__global__ void split_w(const float* __restrict__ w0, const float* __restrict__ w1,
                        const float* __restrict__ w2, const float* __restrict__ w3,
                        int n2)
{
    int wi = blockIdx.y;
    const float* src = (wi == 0) ? w0 : (wi == 1) ? w1 : (wi == 2) ? w2 : w3;
    int i = blockIdx.x * blockDim.x + threadIdx.x;
    if (i >= n2) return;
    split_pair(((const float2*)src)[i], g_wh[wi], g_wl[wi], i);
}

// ---------------------------------------------------------------------------
// HMMA GEMM: C[4096,1024] = A[4096,1024] * B[1024,1024]^T
// 2-stage cp.async, 2 CTAs/SM.   [R12/R13 measured version — unchanged]
// ---------------------------------------------------------------------------
#define GSTR 40
#define GARR (128 * GSTR)              // 5120 bf16 = 10240 B
#define NSTG 2
#define TCG_SMEM (int)(NSTG * 4 * GARR * sizeof(__nv_bfloat16))   // 81920 B

__global__ __launch_bounds__(256, 2)
void tc_gemm(int asel, int wsel, int csel, float* Cparam, const float* bias)
{
    extern __shared__ __nv_bfloat16 smem[];
    const uint32_t sbase = smem_to_u32(smem);

    if (gridDim.z == 3) { wsel = blockIdx.z; csel = blockIdx.z; }

    const __nv_bfloat16* GAh = asel ? g_ch : g_xh;
    const __nv_bfloat16* GAl = asel ? g_cl : g_xl;
    const __nv_bfloat16* GBh = g_wh[wsel];
    const __nv_bfloat16* GBl = g_wl[wsel];

    const int tid  = threadIdx.x;
    const int wid  = tid >> 5;
    const int lane = tid & 31;
    const int wm   = wid >> 2;
    const int wn   = wid & 3;
    const int lr4  = lane >> 2;
    const int kq   = lane & 3;
    const int m0   = blockIdx.y * 128;
    const int n0   = blockIdx.x * 128;

    const int lrow0 = tid >> 2;
    const int lch   = tid & 3;
    const uint32_t sd0 = (uint32_t)(lrow0 * GSTR + lch * 8) * 2;
    const uint32_t sd1 = (uint32_t)((lrow0 + 64) * GSTR + lch * 8) * 2;

    const uint32_t aoff = (uint32_t)((wm * 64 + (lane & 15)) * GSTR + ((lane >> 4) & 1) * 8) * 2;
    const uint32_t boff = (uint32_t)((wn * 32 + (lane & 7) + ((lane >> 4) & 1) * 8) * GSTR
                                     + ((lane >> 3) & 1) * 8) * 2;

    float c[4][4][4];
#pragma unroll
    for (int i = 0; i < 4; i++)
#pragma unroll
        for (int j = 0; j < 4; j++)
#pragma unroll
            for (int e = 0; e < 4; e++) c[i][j][e] = 0.f;

#define ISSUE_STAGE(t) do { \
        uint32_t sb_ = sbase + (uint32_t)(((t) % NSTG) * 4 * GARR) * 2; \
        size_t koA0_ = (size_t)(m0 + lrow0) * DM + (size_t)(t) * 32 + lch * 8; \
        size_t koA1_ = (size_t)(m0 + lrow0 + 64) * DM + (size_t)(t) * 32 + lch * 8; \
        size_t koB0_ = (size_t)(n0 + lrow0) * DM + (size_t)(t) * 32 + lch * 8; \
        size_t koB1_ = (size_t)(n0 + lrow0 + 64) * DM + (size_t)(t) * 32 + lch * 8; \
        cp16(sb_ + sd0,                GAh + koA0_); \
        cp16(sb_ + sd1,                GAh + koA1_); \
        cp16(sb_ + GARR * 2 + sd0,     GAl + koA0_); \
        cp16(sb_ + GARR * 2 + sd1,     GAl + koA1_); \
        cp16(sb_ + 2 * GARR * 2 + sd0, GBh + koB0_); \
        cp16(sb_ + 2 * GARR * 2 + sd1, GBh + koB1_); \
        cp16(sb_ + 3 * GARR * 2 + sd0, GBl + koB0_); \
        cp16(sb_ + 3 * GARR * 2 + sd1, GBl + koB1_); \
        CP_COMMIT(); \
    } while (0)

    ISSUE_STAGE(0);
    ISSUE_STAGE(1);

    for (int t = 0; t < 32; t++) {
        if (t == 31) CP_WAIT0(); else CP_WAIT1();
        __syncthreads();

        const uint32_t stg = sbase + (uint32_t)((t % NSTG) * 4 * GARR) * 2;

#pragma unroll
        for (int kh = 0; kh < 2; kh++) {
            const uint32_t ko = (uint32_t)(kh * 16) * 2;
            uint32_t ah[4][4], al[4][4], bh[2][4], bl[2][4];
#pragma unroll
            for (int i = 0; i < 4; i++) {
                ldsm4(ah[i], stg + aoff + ko + (uint32_t)(i * 16 * GSTR) * 2);
                ldsm4(al[i], stg + GARR * 2 + aoff + ko + (uint32_t)(i * 16 * GSTR) * 2);
            }
#pragma unroll
            for (int jj = 0; jj < 2; jj++) {
                ldsm4(bh[jj], stg + 2 * GARR * 2 + boff + ko + (uint32_t)(jj * 16 * GSTR) * 2);
                ldsm4(bl[jj], stg + 3 * GARR * 2 + boff + ko + (uint32_t)(jj * 16 * GSTR) * 2);
            }

#pragma unroll
            for (int i = 0; i < 4; i++)
#pragma unroll
                for (int j = 0; j < 4; j++) {
                    const uint32_t* fh = bh[j >> 1] + (j & 1) * 2;
                    const uint32_t* fl = bl[j >> 1] + (j & 1) * 2;
                    mma16816(c[i][j], ah[i], fh);
                    mma16816(c[i][j], ah[i], fl);
                    mma16816(c[i][j], al[i], fh);
                }
        }

        __syncthreads();                  // all warps done with slot t%2
        if (t + 2 < 32) ISSUE_STAGE(t + 2);
    }
#undef ISSUE_STAGE

    if (csel < 3) {
        __nv_bfloat16* Hd = (csel == 0) ? g_qh : (csel == 1) ? g_kh : g_vh;
        __nv_bfloat16* Ld = (csel == 0) ? g_ql : (csel == 1) ? g_kl : g_vl;
        const float scale = (csel == 0) ? 0.125f : 1.0f;
#pragma unroll
        for (int i = 0; i < 4; i++) {
            int r = m0 + wm * 64 + i * 16 + lr4;
#pragma unroll
            for (int j = 0; j < 4; j++) {
                int col = n0 + wn * 32 + j * 8 + kq * 2;
#pragma unroll
                for (int half = 0; half < 2; half++) {
                    int rr = r + half * 8;
                    float v0 = c[i][j][half * 2 + 0] * scale;
                    float v1 = c[i][j][half * 2 + 1] * scale;
                    __nv_bfloat16 h0 = __float2bfloat16(v0);
                    __nv_bfloat16 h1 = __float2bfloat16(v1);
                    __nv_bfloat16 l0 = __float2bfloat16(v0 - __bfloat162float(h0));
                    __nv_bfloat16 l1 = __float2bfloat16(v1 - __bfloat162float(h1));
                    *(__nv_bfloat162*)&Hd[(size_t)rr * DM + col] = __halves2bfloat162(h0, h1);
                    *(__nv_bfloat162*)&Ld[(size_t)rr * DM + col] = __halves2bfloat162(l0, l1);
                }
            }
        }
    } else {
#pragma unroll
        for (int i = 0; i < 4; i++) {
            int r = m0 + wm * 64 + i * 16 + lr4;
#pragma unroll
            for (int j = 0; j < 4; j++) {
                int col = n0 + wn * 32 + j * 8 + kq * 2;
                float bx = bias[col], by = bias[col + 1];
                *(float2*)(Cparam + (size_t)r * DM + col)       = make_float2(c[i][j][0] + bx, c[i][j][1] + by);
                *(float2*)(Cparam + (size_t)(r + 8) * DM + col) = make_float2(c[i][j][2] + bx, c[i][j][3] + by);
            }
        }
    }
}

// ---------------------------------------------------------------------------
// MMA flash attention, causal. Br=64 (128 threads, 4 warps x 16 rows),
// Bc=64 KV blocks, double-buffered cp.async. Smem 92160 B -> 2 CTAs/SM:
// independent CTAs decorrelate softmax phases, covering the tensor pipe.
// Numerics identical to R11/R13 (3-term hi/lo everywhere).
// ---------------------------------------------------------------------------
#define ASTR 72
#define A64  (64 * ASTR)                // 4608 bf16 per 64x64 tile
#define ATTN_SMEM (int)((2 * A64 + 2 * 4 * A64) * sizeof(__nv_bfloat16))  // 92160 B

__device__ __forceinline__ void kv_load64(uint32_t sbase, int tid, int kb, int buf, int hoff)
{
#pragma unroll
    for (int i = 0; i < 16; i++) {
        int id  = tid + 128 * i;
        int arr = id >> 9;          // 512 chunks per array
        int rem = id & 511;
        int row = rem >> 3;
        int ch  = rem & 7;
        const __nv_bfloat16* src =
            ((arr == 0) ? g_kh : (arr == 1) ? g_kl : (arr == 2) ? g_vh : g_vl)
            + (size_t)(kb * 64 + row) * DM + hoff + ch * 8;
        uint32_t dst = sbase + (uint32_t)(2 * A64 + buf * 4 * A64 + arr * A64
                                          + row * ASTR + ch * 8) * 2;
        cp16(dst, src);
    }
}

__global__ __launch_bounds__(128, 2)
void attn_mma()
{
    extern __shared__ __nv_bfloat16 asm_sm[];
    const uint32_t sbase = smem_to_u32(asm_sm);

    const int qb   = gridDim.x - 1 - blockIdx.x;    // reversed: long CTAs first
    const int h    = blockIdx.y;
    const int hoff = h * HDIM;
    const int tid  = threadIdx.x;
    const int wid  = tid >> 5;         // 0..3
    const int lane = tid & 31;
    const int lr4  = lane >> 2;
    const int kq   = lane & 3;

    // Q load (cp.async): 1024 chunks over 128 threads
#pragma unroll
    for (int i = 0; i < 8; i++) {
        int id  = tid + 128 * i;
        int arr = id >> 9;
        int rem = id & 511;
        int row = rem >> 3;
        int ch  = rem & 7;
        const __nv_bfloat16* src = (arr ? g_ql : g_qh)
            + (size_t)(qb * 64 + row) * DM + hoff + ch * 8;
        uint32_t dst = sbase + (uint32_t)(arr * A64 + row * ASTR + ch * 8) * 2;
        cp16(dst, src);
    }
    kv_load64(sbase, tid, 0, 0, hoff);
    CP_COMMIT();

    const uint32_t qoff = (uint32_t)((wid * 16 + (lane & 7) + ((lane >> 3) & 1) * 8) * ASTR
                                     + ((lane >> 4) & 1) * 8);
    const uint32_t koff = (uint32_t)(((lane & 7) + ((lane >> 4) & 1) * 8) * ASTR
                                     + ((lane >> 3) & 1) * 8);
    const uint32_t voff = (uint32_t)(((lane & 7) + ((lane >> 3) & 1) * 8) * ASTR
                                     + ((lane >> 4) & 1) * 8);

    float o[8][4];
#pragma unroll
    for (int i = 0; i < 8; i++)
#pragma unroll
        for (int e = 0; e < 4; e++) o[i][e] = 0.f;
    float m_lo = -1e30f, m_hi = -1e30f, l_lo = 0.f, l_hi = 0.f;

    for (int kb = 0; kb <= qb; kb++) {
        const int buf = kb & 1;
        if (kb < qb) {
            kv_load64(sbase, tid, kb + 1, buf ^ 1, hoff);
            CP_COMMIT();
            CP_WAIT1();
        } else {
            CP_WAIT0();
        }
        __syncthreads();

        const uint32_t Qh_b = sbase;
        const uint32_t Ql_b = sbase + (uint32_t)A64 * 2;
        const uint32_t Kh_b = sbase + (uint32_t)(2 * A64 + buf * 4 * A64) * 2;
        const uint32_t Kl_b = Kh_b + (uint32_t)A64 * 2;
        const uint32_t Vh_b = Kh_b + (uint32_t)(2 * A64) * 2;
        const uint32_t Vl_b = Kh_b + (uint32_t)(3 * A64) * 2;

        // ---- S = Q K^T (warp: 16 rows x 64 cols) ----
        float s[8][4];
#pragma unroll
        for (int j = 0; j < 8; j++)
#pragma unroll
            for (int e = 0; e < 4; e++) s[j][e] = 0.f;

#pragma unroll
        for (int ks = 0; ks < 4; ks++) {
            uint32_t ah[4], al[4];
            ldsm4(ah, Qh_b + (qoff + ks * 16) * 2);
            ldsm4(al, Ql_b + (qoff + ks * 16) * 2);
#pragma unroll
            for (int jp = 0; jp < 4; jp++) {
                uint32_t bh[4], bl[4];
                ldsm4(bh, Kh_b + (koff + jp * 16 * ASTR + ks * 16) * 2);
                ldsm4(bl, Kl_b + (koff + jp * 16 * ASTR + ks * 16) * 2);
                mma16816(s[2 * jp],     ah, bh);
                mma16816(s[2 * jp],     ah, bl);
                mma16816(s[2 * jp],     al, bh);
                mma16816(s[2 * jp + 1], ah, bh + 2);
                mma16816(s[2 * jp + 1], ah, bl + 2);
                mma16816(s[2 * jp + 1], al, bh + 2);
            }
        }

        // ---- causal mask (diag block only) ----
        if (kb == qb) {
            const int rl = wid * 16 + lr4;
#pragma unroll
            for (int j = 0; j < 8; j++) {
                int c0 = j * 8 + kq * 2;
                if (c0     > rl)     s[j][0] = -1e30f;
                if (c0 + 1 > rl)     s[j][1] = -1e30f;
                if (c0     > rl + 8) s[j][2] = -1e30f;
                if (c0 + 1 > rl + 8) s[j][3] = -1e30f;
            }
        }

        // ---- online softmax ----
        float bm_lo = -1e30f, bm_hi = -1e30f;
#pragma unroll
        for (int j = 0; j < 8; j++) {
            bm_lo = fmaxf(bm_lo, fmaxf(s[j][0], s[j][1]));
            bm_hi = fmaxf(bm_hi, fmaxf(s[j][2], s[j][3]));
        }
#pragma unroll
        for (int off = 1; off <= 2; off <<= 1) {
            bm_lo = fmaxf(bm_lo, __shfl_xor_sync(0xffffffffu, bm_lo, off));
            bm_hi = fmaxf(bm_hi, __shfl_xor_sync(0xffffffffu, bm_hi, off));
        }
        const float mn_lo = fmaxf(m_lo, bm_lo);
        const float mn_hi = fmaxf(m_hi, bm_hi);
        const float cor_lo = __expf(m_lo - mn_lo);
        const float cor_hi = __expf(m_hi - mn_hi);
        m_lo = mn_lo; m_hi = mn_hi;

        float sum_lo = 0.f, sum_hi = 0.f;
#pragma unroll
        for (int j = 0; j < 8; j++) {
            s[j][0] = __expf(s[j][0] - mn_lo);
            s[j][1] = __expf(s[j][1] - mn_lo);
            s[j][2] = __expf(s[j][2] - mn_hi);
            s[j][3] = __expf(s[j][3] - mn_hi);
            sum_lo += s[j][0] + s[j][1];
            sum_hi += s[j][2] + s[j][3];
        }
#pragma unroll
        for (int off = 1; off <= 2; off <<= 1) {
            sum_lo += __shfl_xor_sync(0xffffffffu, sum_lo, off);
            sum_hi += __shfl_xor_sync(0xffffffffu, sum_hi, off);
        }
        l_lo = l_lo * cor_lo + sum_lo;
        l_hi = l_hi * cor_hi + sum_hi;
#pragma unroll
        for (int j2 = 0; j2 < 8; j2++) {
            o[j2][0] *= cor_lo; o[j2][1] *= cor_lo;
            o[j2][2] *= cor_hi; o[j2][3] *= cor_hi;
        }

        // ---- O += P V (64 kv rows x 64 d) ----
#pragma unroll
        for (int ks2 = 0; ks2 < 4; ks2++) {
            const int j0 = 2 * ks2, j1 = 2 * ks2 + 1;
            uint32_t ph[4], pl[4];
#pragma unroll
            for (int q4 = 0; q4 < 4; q4++) {
                const float p0 = (q4 < 2) ? s[j0][(q4 & 1) * 2]     : s[j1][(q4 & 1) * 2];
                const float p1 = (q4 < 2) ? s[j0][(q4 & 1) * 2 + 1] : s[j1][(q4 & 1) * 2 + 1];
                uint32_t hp = packbf(p0, p1);
                __nv_bfloat162 hb = *(__nv_bfloat162*)&hp;
                float r0 = p0 - __bfloat162float(hb.x);
                float r1 = p1 - __bfloat162float(hb.y);
                ph[q4] = hp;
                pl[q4] = packbf(r0, r1);
            }
#pragma unroll
            for (int jp2 = 0; jp2 < 4; jp2++) {
                uint32_t vh[4], vl[4];
                ldsm4t(vh, Vh_b + (voff + ks2 * 16 * ASTR + jp2 * 16) * 2);
                ldsm4t(vl, Vl_b + (voff + ks2 * 16 * ASTR + jp2 * 16) * 2);
                mma16816(o[2 * jp2],     ph, vh);
                mma16816(o[2 * jp2],     ph, vl);
                mma16816(o[2 * jp2],     pl, vh);
                mma16816(o[2 * jp2 + 1], ph, vh + 2);
                mma16816(o[2 * jp2 + 1], ph, vl + 2);
                mma16816(o[2 * jp2 + 1], pl, vh + 2);
            }
        }
        __syncthreads();   // done reading buf before next-iter cp.async overwrites it
    }

    // ---- epilogue ----
    const float inv_lo = 1.0f / l_lo;
    const float inv_hi = 1.0f / l_hi;
    const int row_g = qb * 64 + wid * 16 + lr4;
#pragma unroll
    for (int j2 = 0; j2 < 8; j2++) {
        const int col = hoff + j2 * 8 + kq * 2;
        {
            float v0 = o[j2][0] * inv_lo, v1 = o[j2][1] * inv_lo;
            __nv_bfloat16 h0 = __float2bfloat16(v0);
            __nv_bfloat16 h1 = __float2bfloat16(v1);
            __nv_bfloat16 l0 = __float2bfloat16(v0 - __bfloat162float(h0));
            __nv_bfloat16 l1 = __float2bfloat16(v1 - __bfloat162float(h1));
            *(__nv_bfloat162*)&g_ch[(size_t)row_g * DM + col] = __halves2bfloat162(h0, h1);
            *(__nv_bfloat162*)&g_cl[(size_t)row_g * DM + col] = __halves2bfloat162(l0, l1);
        }
        {
            float v0 = o[j2][2] * inv_hi, v1 = o[j2][3] * inv_hi;
            __nv_bfloat16 h0 = __float2bfloat16(v0);
            __nv_bfloat16 h1 = __float2bfloat16(v1);
            __nv_bfloat16 l0 = __float2bfloat16(v0 - __bfloat162float(h0));
            __nv_bfloat16 l1 = __float2bfloat16(v1 - __bfloat162float(h1));
            *(__nv_bfloat162*)&g_ch[(size_t)(row_g + 8) * DM + col] = __halves2bfloat162(h0, h1);
            *(__nv_bfloat162*)&g_cl[(size_t)(row_g + 8) * DM + col] = __halves2bfloat162(l0, l1);
        }
    }
}

// ---------------------------------------------------------------------------
extern "C" void kernel_launch(void* const* d_in, const int* in_sizes, int n_in,
                              void* d_out, int out_size)
{
    const float* x  = (const float*)d_in[0];
    const float* Wq = (const float*)d_in[1];
    const float* Wk = (const float*)d_in[2];
    const float* Wv = (const float*)d_in[3];
    const float* Wo = (const float*)d_in[4];
    const float* bo = (const float*)d_in[5];
    float* out = (float*)d_out;

    cudaFuncSetAttribute(tc_gemm, cudaFuncAttributeMaxDynamicSharedMemorySize, TCG_SMEM);
    cudaFuncSetAttribute(attn_mma, cudaFuncAttributeMaxDynamicSharedMemorySize, ATTN_SMEM);

    const int n2x = SQ * DM / 2;
    const int n2w = DM * DM / 2;

    split_x<<<n2x / 256, 256>>>(x, n2x);
    split_w<<<dim3(n2w / 256, 4), 256>>>(Wq, Wk, Wv, Wo, n2w);

    tc_gemm<<<dim3(DM / 128, SQ / 128, 3), 256, TCG_SMEM>>>(0, 0, 0, nullptr, nullptr);  // QKV

    attn_mma<<<dim3(SQ / 64, NH), 128, ATTN_SMEM>>>();

    tc_gemm<<<dim3(DM / 128, SQ / 128, 1), 256, TCG_SMEM>>>(1, 3, 3, out, bo);           // out proj
}